// round 13
// baseline (speedup 1.0000x reference)
#include <cuda_runtime.h>
#include <cuda_fp16.h>
#include <cstdint>

#define L_SEQ   2048
#define D_MODEL 1024
#define N_HEADS 16
#define D_HEAD  64
#define N_BATCH 2
#define BH      (N_BATCH * N_HEADS)

#define MERGED_BLOCKS 2816      // = 11 * 256 ; bid%11<3 -> qkv (768), else relc (2048)
#define RELC_BLOCKS   2048

// ---------------- device scratch (no allocation) ----------------
__device__ __half g_x[4096 * 1024];          // X single fp16
__device__ __half g_wt[3 * 1024 * 1024];     // [z][n][k] single fp16
__device__ __half g_q[4096 * 1024];          // [BH][L][DH] single fp16
__device__ __half g_k[4096 * 1024];
__device__ __half g_v[4096 * 1024];
__device__ __half g_relc[16 * 2048 * 2048];  // (rel1+rel2)*0.125*log2e, fp16
__device__ float  g_mlc[N_BATCH * L_SEQ];    // mask * log2e

// ---------------- helpers ----------------
__device__ __forceinline__ uint32_t smem_u32(const void* p) {
    uint32_t a;
    asm("{ .reg .u64 t; cvta.to.shared.u64 t, %1; cvt.u32.u64 %0, t; }"
        : "=r"(a) : "l"(p));
    return a;
}
__device__ __forceinline__ uint32_t packh2(float e0, float e1) {
    uint32_t r;   // e0 -> low half, e1 -> high half
    asm("cvt.rn.f16x2.f32 %0, %1, %2;" : "=r"(r) : "f"(e1), "f"(e0));
    return r;
}
__device__ __forceinline__ float ex2f(float x) {
    float y; asm("ex2.approx.f32 %0, %1;" : "=f"(y) : "f"(x)); return y;
}
__device__ __forceinline__ void mma16816h(float* c, const uint32_t* a, const uint32_t* b) {
    asm volatile(
        "mma.sync.aligned.m16n8k16.row.col.f32.f16.f16.f32 "
        "{%0,%1,%2,%3}, {%4,%5,%6,%7}, {%8,%9}, {%0,%1,%2,%3};"
        : "+f"(c[0]), "+f"(c[1]), "+f"(c[2]), "+f"(c[3])
        : "r"(a[0]), "r"(a[1]), "r"(a[2]), "r"(a[3]), "r"(b[0]), "r"(b[1]));
}
__device__ __forceinline__ void ldm4(uint32_t* r, uint32_t a) {
    asm volatile("ldmatrix.sync.aligned.m8n8.x4.shared.b16 {%0,%1,%2,%3}, [%4];"
        : "=r"(r[0]), "=r"(r[1]), "=r"(r[2]), "=r"(r[3]) : "r"(a));
}
__device__ __forceinline__ void ldm4t(uint32_t* r, uint32_t a) {
    asm volatile("ldmatrix.sync.aligned.m8n8.x4.trans.shared.b16 {%0,%1,%2,%3}, [%4];"
        : "=r"(r[0]), "=r"(r[1]), "=r"(r[2]), "=r"(r[3]) : "r"(a));
}
__device__ __forceinline__ void cp16(uint32_t dst, const void* src) {
    asm volatile("cp.async.cg.shared.global [%0], [%1], 16;" :: "r"(dst), "l"(src));
}
#define CP_COMMIT() asm volatile("cp.async.commit_group;" ::: "memory")
#define CP_WAIT(n)  asm volatile("cp.async.wait_group %0;" :: "n"(n) : "memory")
#define GBAR(id)    asm volatile("bar.sync %0, 128;" :: "r"(id) : "memory")

// ---------------- Kernel A: X -> single fp16 ----------------
__global__ void conv_x_kernel(const float* __restrict__ X) {
    size_t i = ((size_t)blockIdx.x * 256 + threadIdx.x) * 4;
    float4 v = *(const float4*)(X + i);
    *(uint2*)(g_x + i) = make_uint2(packh2(v.x, v.y), packh2(v.z, v.w));
}

// ---------------- Kernel A2: mask * log2e ----------------
__global__ void mask_kernel(const float* __restrict__ mask) {
    int i = blockIdx.x * 256 + threadIdx.x;
    g_mlc[i] = mask[i] * 1.4426950409f;
}

// ---------------- Kernel B: W[k][n] -> Wt[n][k] single fp16 ----------------
__global__ void conv_w_kernel(const float* __restrict__ Wq,
                              const float* __restrict__ Wk,
                              const float* __restrict__ Wv) {
    __shared__ float t[32][33];
    int z = blockIdx.z;
    const float* W = (z == 0) ? Wq : (z == 1) ? Wk : Wv;
    int n0 = blockIdx.x * 32, k0 = blockIdx.y * 32;
    int tx = threadIdx.x, ty = threadIdx.y;
#pragma unroll
    for (int i = 0; i < 4; i++)
        t[ty + 8*i][tx] = W[(size_t)(k0 + ty + 8*i) * D_MODEL + n0 + tx];
    __syncthreads();
    size_t base = (size_t)z * 1024 * 1024;
#pragma unroll
    for (int i = 0; i < 4; i++)
        g_wt[base + (size_t)(n0 + ty + 8*i) * 1024 + k0 + tx] =
            __float2half_rn(t[tx][ty + 8*i]);
}

// ---------------------------------------------------------------------------
// Kernel C (merged, interleaved): bid%11<3 -> QKV GEMM tile; else relc stream.
// ---------------------------------------------------------------------------
__global__ __launch_bounds__(256, 2) void qkv_relc_kernel(
    const float* __restrict__ bq, const float* __restrict__ bk,
    const float* __restrict__ bv,
    const float* __restrict__ rel1, const float* __restrict__ rel2)
{
    const int grp = blockIdx.x / 11, sl = blockIdx.x % 11;
    if (sl >= 3) {
        const float C = 0.1803368801f;   // 0.125 * log2(e)
        const int rbid = grp * 8 + (sl - 3);
        size_t base = ((size_t)rbid * 256 + threadIdx.x) * 4;
        const size_t stride = (size_t)RELC_BLOCKS * 256 * 4;
#pragma unroll 4
        for (int it = 0; it < 32; it++) {
            size_t i = base + (size_t)it * stride;
            float4 a = *(const float4*)(rel1 + i);
            float4 b = *(const float4*)(rel2 + i);
            *(uint2*)(g_relc + i) = make_uint2(
                packh2((a.x + b.x) * C, (a.y + b.y) * C),
                packh2((a.z + b.z) * C, (a.w + b.w) * C));
        }
        return;
    }

    extern __shared__ char smem[];
    const uint32_t sb = smem_u32(smem);
    const int qid = grp * 3 + sl;
    const int z = qid >> 8;
    const int rem = qid & 255;
    const int n0 = (rem & 7) * 128, m0 = (rem >> 3) * 128;
    const float* bias = (z == 0) ? bq : (z == 1) ? bk : bv;
    __half* outp = (z == 0) ? g_q : (z == 1) ? g_k : g_v;
    const __half* wt = g_wt + (size_t)z * 1024 * 1024;

    const int tid = threadIdx.x, lane = tid & 31, wid = tid >> 5;
    const int gid = lane >> 2, tg = lane & 3;
    const int wm = wid >> 1, wn = wid & 1;
    const int lrow = (lane & 7) + ((lane >> 3) & 1) * 8;
    const int lcolb = (lane >> 4) * 16;

    auto stage = [&](int kc, int buf) {
#pragma unroll
        for (int i = 0; i < 4; i++) {
            int f = i * 256 + tid;
            int tensor = f >> 9, rr = f & 511, r = rr >> 2, c = rr & 3;
            uint32_t dst = sb + buf * 20480 + tensor * 10240 + r * 80 + c * 16;
            const __half* src = tensor
                ? wt  + (size_t)(n0 + r) * 1024 + kc * 32 + c * 8
                : g_x + (size_t)(m0 + r) * 1024 + kc * 32 + c * 8;
            cp16(dst, src);
        }
        CP_COMMIT();
    };

    float acc[2][8][4];
#pragma unroll
    for (int mt = 0; mt < 2; mt++)
#pragma unroll
        for (int nt = 0; nt < 8; nt++)
#pragma unroll
            for (int q = 0; q < 4; q++) acc[mt][nt][q] = 0.0f;

    stage(0, 0);
    for (int kc = 0; kc < 32; kc++) {
        const int buf = kc & 1;
        CP_WAIT(0);
        __syncthreads();
        if (kc < 31) stage(kc + 1, buf ^ 1);

        const uint32_t ab = sb + buf * 20480;
#pragma unroll
        for (int ks = 0; ks < 2; ks++) {
            const int kboff = ks * 32 + lcolb;
            uint32_t af[2][4];
#pragma unroll
            for (int mt = 0; mt < 2; mt++)
                ldm4(af[mt], ab + (wm * 32 + mt * 16 + lrow) * 80 + kboff);
#pragma unroll
            for (int g = 0; g < 4; g++) {
                uint32_t b4[4];
                ldm4(b4, ab + 10240 + (wn * 64 + g * 16 + lrow) * 80 + kboff);
#pragma unroll
                for (int sub = 0; sub < 2; sub++) {
                    uint32_t b2[2] = {b4[sub], b4[sub + 2]};
                    const int nt = g * 2 + sub;
                    mma16816h(acc[0][nt], af[0], b2);
                    mma16816h(acc[1][nt], af[1], b2);
                }
            }
        }
    }

#pragma unroll
    for (int mt = 0; mt < 2; mt++) {
#pragma unroll
        for (int nt = 0; nt < 8; nt++) {
            int n = n0 + wn * 64 + nt * 8 + tg * 2;
            int hh = n >> 6, d = n & 63;
            float b0 = bias[n], b1 = bias[n + 1];
            int mA = m0 + wm * 32 + mt * 16 + gid;
#pragma unroll
            for (int half = 0; half < 2; half++) {
                int m = mA + half * 8;
                int bb = m >> 11, ll = m & 2047;
                size_t dst = (((size_t)(bb * N_HEADS + hh)) * L_SEQ + ll) * D_HEAD + d;
                *(uint32_t*)(outp + dst) =
                    packh2(acc[mt][nt][half * 2] + b0,
                           acc[mt][nt][half * 2 + 1] + b1);
            }
        }
    }
}

// ---------------------------------------------------------------------------
// Kernel D: attention (fp16, 1-pass), TWO independent 4-warp groups per CTA,
// de-phased so one group's HMMAs overlap the other's exp epilogue per SMSP.
// cp.async publication rule: wait_group is PER-THREAD, so every CP_WAIT is
// followed by the group's named barrier before the staged data is consumed
// (this was the R12 NaN bug).
// Ledger per group: prologue commit {Q,KV0}; iter jt commits {RCjt},{KVjt+1};
// WAIT(2)+GBAR -> KV(jt) visible; WAIT(1)+GBAR -> RC(jt) visible.
// smem per group: Q 9216 + K 2x9216 + V 2x9216 + RC 9216 = 55296; x2 =
// 110592 B -> 2 CTAs/SM.
// ---------------------------------------------------------------------------
__global__ __launch_bounds__(256, 2) void attn_mma_kernel(float* __restrict__ out)
{
    extern __shared__ char smem[];
    const uint32_t sb = smem_u32(smem);

    const int tid = threadIdx.x, lane = tid & 31;
    const int g = tid >> 7;                 // group 0/1 (warps 0-3 / 4-7)
    const int wg_tid = tid & 127;
    const int w4 = wg_tid >> 5;             // warp within group
    const int gid = lane >> 2, tg = lane & 3;
    const int bh = blockIdx.y, b = bh >> 4, h = bh & 15;
    const int i0 = blockIdx.x * 128;
    const int lrow = (lane & 7) + ((lane >> 3) & 1) * 8;
    const int lcolb = (lane >> 4) * 16;
    const float C = 0.1803368801f;           // 0.125 * log2(e)

    const uint32_t GB = sb + g * 55296;      // group smem base
    const uint32_t QS = GB, KSs = GB + 9216, VSs = GB + 27648, RCs = GB + 46080;

    const __half* qp = g_q + (size_t)bh * L_SEQ * D_HEAD;
    const __half* kp = g_k + (size_t)bh * L_SEQ * D_HEAD;
    const __half* vp = g_v + (size_t)bh * L_SEQ * D_HEAD;
    const __half* rcg = g_relc + (size_t)h * L_SEQ * L_SEQ;
    const float* mlp = g_mlc + (size_t)b * L_SEQ;

    const int grow = i0 + g * 64;            // group's first global q-row
    const int r0 = grow + w4 * 16 + gid, r1 = r0 + 8;

    auto stage_kv = [&](int jt, int buf) {   // K+V tile (group-local)
        const int j0 = jt * 64;
#pragma unroll
        for (int i = 0; i < 8; i++) {
            int f = i * 128 + wg_tid;
            int tensor = f >> 9, rr = f & 511, r = rr >> 3, c = rr & 7;
            uint32_t dst = (tensor ? VSs : KSs) + buf * 9216 + r * 144 + c * 16;
            const __half* src = tensor ? vp : kp;
            cp16(dst, src + (size_t)(j0 + r) * 64 + c * 8);
        }
        CP_COMMIT();
    };
    auto stage_rc = [&](int jt) {            // RC tile: group's 64 rows
        const int j0 = jt * 64;
#pragma unroll
        for (int i = 0; i < 4; i++) {
            int f = i * 128 + wg_tid;
            int r = f >> 3, c = f & 7;
            cp16(RCs + r * 144 + c * 16,
                 rcg + (size_t)(grow + r) * L_SEQ + j0 + c * 8);
        }
        CP_COMMIT();
    };

    // prologue: Q (group rows) + KV(0), one commit group
    {
#pragma unroll
        for (int i = 0; i < 4; i++) {
            int f = i * 128 + wg_tid;
            int r = f >> 3, c = f & 7;
            cp16(QS + r * 144 + c * 16, qp + (size_t)(grow + r) * 64 + c * 8);
        }
#pragma unroll
        for (int i = 0; i < 8; i++) {
            int f = i * 128 + wg_tid;
            int tensor = f >> 9, rr = f & 511, r = rr >> 3, c = rr & 7;
            uint32_t dst = (tensor ? VSs : KSs) + r * 144 + c * 16;
            const __half* src = tensor ? vp : kp;
            cp16(dst, src + (size_t)r * 64 + c * 8);
        }
        CP_COMMIT();
    }

    float o[8][4];
#pragma unroll
    for (int nt = 0; nt < 8; nt++)
#pragma unroll
        for (int q = 0; q < 4; q++) o[nt][q] = 0.0f;
    float lsum0 = 0.0f, lsum1 = 0.0f;

    const int rowA = w4 * 16 + gid, rowB = rowA + 8;

    for (int jt = 0; jt < 32; jt++) {
        const int j0 = jt * 64;
        const int buf = jt & 1;
        GBAR(1 + g);                 // write-after-read guard (RC, KV bufs)
        stage_rc(jt);                // commit {RC(jt)}
        stage_kv((jt + 1) & 31, buf ^ 1);  // commit {KV(jt+1)} (wrap unused)
        CP_WAIT(2);                  // own copies of KV(jt) [+Q at jt=0] done
        GBAR(1 + g);                 // publish: all group threads' KV(jt)/Q

        // ---- S = Q K^T (1-pass) ----
        float s[8][4];
#pragma unroll
        for (int nt = 0; nt < 8; nt++)
#pragma unroll
            for (int q = 0; q < 4; q++) s[nt][q] = 0.0f;
        const uint32_t kb_base = KSs + buf * 9216;
#pragma unroll
        for (int ks = 0; ks < 4; ks++) {
            const int kboff = ks * 32 + lcolb;
            uint32_t q4[4];
            ldm4(q4, QS + (w4 * 16 + lrow) * 144 + kboff);
#pragma unroll
            for (int gg = 0; gg < 4; gg++) {
                uint32_t k4[4];
                ldm4(k4, kb_base + (gg * 16 + lrow) * 144 + kboff);
#pragma unroll
                for (int sub = 0; sub < 2; sub++) {
                    uint32_t b2[2] = {k4[sub], k4[sub + 2]};
                    mma16816h(s[gg * 2 + sub], q4, b2);
                }
            }
        }

        CP_WAIT(1);                  // own RC(jt) copies done
        GBAR(1 + g);                 // publish RC(jt) group-wide

        // ---- epilogue: p = 2^( s*C + relC + mlc ) -> fp16 ----
        uint32_t pw[8][2];
#pragma unroll
        for (int nt = 0; nt < 8; nt++) {
            const int jo = nt * 8 + tg * 2;
            float2 rcA = __half22float2(
                *(const __half2*)(smem + (RCs - sb) + rowA * 144 + jo * 2));
            float2 rcB = __half22float2(
                *(const __half2*)(smem + (RCs - sb) + rowB * 144 + jo * 2));
            float2 mk = *(const float2*)(mlp + j0 + jo);
            float p00 = ex2f(fmaf(s[nt][0], C, rcA.x + mk.x));
            float p01 = ex2f(fmaf(s[nt][1], C, rcA.y + mk.y));
            float p10 = ex2f(fmaf(s[nt][2], C, rcB.x + mk.x));
            float p11 = ex2f(fmaf(s[nt][3], C, rcB.y + mk.y));
            lsum0 += p00 + p01;
            lsum1 += p10 + p11;
            pw[nt][0] = packh2(p00, p01);
            pw[nt][1] = packh2(p10, p11);
        }

        // ---- O += P V (1-pass, V via ldmatrix.trans) ----
        const uint32_t vb_base = VSs + buf * 9216;
#pragma unroll
        for (int ks = 0; ks < 4; ks++) {
            uint32_t a4[4] = {pw[2*ks][0], pw[2*ks][1],
                              pw[2*ks+1][0], pw[2*ks+1][1]};
#pragma unroll
            for (int gg = 0; gg < 4; gg++) {
                uint32_t v4[4];
                ldm4t(v4, vb_base + (ks * 16 + lrow) * 144 + gg * 32 + lcolb);
#pragma unroll
                for (int sub = 0; sub < 2; sub++) {
                    uint32_t b2[2] = {v4[sub * 2], v4[sub * 2 + 1]};
                    mma16816h(o[gg * 2 + sub], a4, b2);
                }
            }
        }
    }
    CP_WAIT(0);

    lsum0 += __shfl_xor_sync(0xffffffffu, lsum0, 1);
    lsum0 += __shfl_xor_sync(0xffffffffu, lsum0, 2);
    lsum1 += __shfl_xor_sync(0xffffffffu, lsum1, 1);
    lsum1 += __shfl_xor_sync(0xffffffffu, lsum1, 2);
    float inv0 = 1.0f / lsum0, inv1 = 1.0f / lsum1;

#pragma unroll
    for (int nt = 0; nt < 8; nt++) {
        int d = nt * 8 + tg * 2;
        *(float2*)(out + ((size_t)b * L_SEQ + r0) * D_MODEL + h * 64 + d) =
            make_float2(o[nt][0] * inv0, o[nt][1] * inv0);
        *(float2*)(out + ((size_t)b * L_SEQ + r1) * D_MODEL + h * 64 + d) =
            make_float2(o[nt][2] * inv1, o[nt][3] * inv1);
    }
}

// ---------------- launch ----------------
extern "C" void kernel_launch(void* const* d_in, const int* in_sizes, int n_in,
                              void* d_out, int out_size)
{
    const float* hidden = (const float*)d_in[0];
    const float* mask   = (const float*)d_in[1];
    const float* rel1   = (const float*)d_in[2];
    const float* rel2   = (const float*)d_in[3];
    const float* Wq = (const float*)d_in[4];
    const float* bq = (const float*)d_in[5];
    const float* Wk = (const float*)d_in[6];
    const float* bk = (const float*)d_in[7];
    const float* Wv = (const float*)d_in[8];
    const float* bv = (const float*)d_in[9];
    float* out = (float*)d_out;

    conv_x_kernel<<<4096, 256>>>(hidden);
    mask_kernel<<<16, 256>>>(mask);
    conv_w_kernel<<<dim3(32, 32, 3), dim3(32, 8)>>>(Wq, Wk, Wv);

    cudaFuncSetAttribute(qkv_relc_kernel,
                         cudaFuncAttributeMaxDynamicSharedMemorySize, 40960);
    qkv_relc_kernel<<<MERGED_BLOCKS, 256, 40960>>>(bq, bk, bv, rel1, rel2);

    cudaFuncSetAttribute(attn_mma_kernel,
                         cudaFuncAttributeMaxDynamicSharedMemorySize, 110592);
    attn_mma_kernel<<<dim3(16, BH), 256, 110592>>>(out);
}